// round 3
// baseline (speedup 1.0000x reference)
#include <cuda_runtime.h>
#include <math.h>

#define TT 60
#define BB 64
#define SS 256
#define DD 1024
#define HH 20

// ---- scratch (static device globals: allowed; no runtime allocation) ----
__device__ float g_w[TT][HH];            // history softmax weights per step
__device__ float g_attn_w[TT*BB*SS];     // windowed attention  [(t*B+b)*S+s]
__device__ float g_query_s[TT*BB*DD];    // windowed queries    [(t*B+b)*D+d]
__device__ float g_qT[BB*DD*64];         // (query_s @ Wq) transposed: [b][d][t(pad64)]
__device__ float g_Eq[TT*BB*SS];         // e . qWq  [(t*B+b)*S+s]
__device__ float g_rp[TT*BB];            // remove_prob [t*B+b]
__device__ float g_ap[TT*BB];            // add_prob
__device__ float g_eW1[BB*SS];           // e . Wn[:D]
__device__ float g_eW2[BB*SS];           // e . Wn[D:]
__device__ float g_Wt2[BB*SS*64];        // sel weights attn_i*g_i : [b][s][t(pad64)]

__device__ __forceinline__ float sigf(float x){ return 1.0f/(1.0f+expf(-x)); }

// ---- step-weight table: w[i][j] applies to history item j steps back ----
__global__ void k_weights(){
    int i = threadIdx.x;
    if (i >= TT) return;
    int k = min(i+1, HH);
    float Z = 0.f;
    for (int j = 0; j < k; j++) Z += expf((20.f - (float)j) / 20.f);
    for (int j = 0; j < HH; j++)
        g_w[i][j] = (j < k) ? expf((20.f - (float)j) / 20.f) / Z : 0.f;
}

// ---- 20-tap window over attns: attn_w[t,b,s] ----
__global__ void k_window_attn(const float* __restrict__ at){
    int idx = blockIdx.x*blockDim.x + threadIdx.x;
    if (idx >= TT*BB*SS) return;
    int s = idx % SS; int b = (idx / SS) % BB; int t = idx / (SS*BB);
    int k = min(t+1, HH);
    float acc = 0.f;
    for (int j = 0; j < k; j++)
        acc = fmaf(g_w[t][j], at[(b*TT + (t-j))*SS + s], acc);
    g_attn_w[idx] = acc;
}

// ---- 20-tap window over queries: query_s[t,b,d] ----
__global__ void k_window_query(const float* __restrict__ q){
    int idx = blockIdx.x*blockDim.x + threadIdx.x;
    if (idx >= TT*BB*DD) return;
    int d = idx % DD; int b = (idx / DD) % BB; int t = idx / (DD*BB);
    int k = min(t+1, HH);
    float acc = 0.f;
    for (int j = 0; j < k; j++)
        acc = fmaf(g_w[t][j], q[(b*TT + (t-j))*DD + d], acc);
    g_query_s[idx] = acc;
}

// ---- gates: rp/ap[t,b] = sigmoid(q_i . W + bias), one warp per (t,b) ----
__global__ void k_gates(const float* __restrict__ q, const float* __restrict__ Wr,
                        const float* __restrict__ br, const float* __restrict__ Wa,
                        const float* __restrict__ ba){
    int w = (blockIdx.x*blockDim.x + threadIdx.x) >> 5;
    int lane = threadIdx.x & 31;
    if (w >= TT*BB) return;
    int t = w / BB, b = w % BB;
    const float* qr = q + (size_t)(b*TT + t)*DD;
    float s1 = 0.f, s2 = 0.f;
    for (int d = lane*4; d < DD; d += 128){
        float4 qv = *(const float4*)(qr + d);
        float4 r4 = *(const float4*)(Wr + d);
        float4 a4 = *(const float4*)(Wa + d);
        s1 += qv.x*r4.x + qv.y*r4.y + qv.z*r4.z + qv.w*r4.w;
        s2 += qv.x*a4.x + qv.y*a4.y + qv.z*a4.z + qv.w*a4.w;
    }
    for (int o = 16; o; o >>= 1){
        s1 += __shfl_xor_sync(0xffffffffu, s1, o);
        s2 += __shfl_xor_sync(0xffffffffu, s2, o);
    }
    if (lane == 0){
        g_rp[w] = sigf(s1 + br[0]);
        g_ap[w] = sigf(s2 + ba[0]);
    }
}

// ---- eW1/eW2[b,s] = e[b,s,:].Wn[:D], e[b,s,:].Wn[D:] — one warp per row ----
__global__ void k_eW(const float* __restrict__ e, const float* __restrict__ Wn){
    int w = (blockIdx.x*blockDim.x + threadIdx.x) >> 5;
    int lane = threadIdx.x & 31;
    if (w >= BB*SS) return;
    const float* er = e + (size_t)w*DD;
    float s1 = 0.f, s2 = 0.f;
    for (int d = lane*4; d < DD; d += 128){
        float4 ev = *(const float4*)(er + d);
        float4 w1 = *(const float4*)(Wn + d);
        float4 w2 = *(const float4*)(Wn + DD + d);
        s1 += ev.x*w1.x + ev.y*w1.y + ev.z*w1.z + ev.w*w1.w;
        s2 += ev.x*w2.x + ev.y*w2.y + ev.z*w2.z + ev.w*w2.w;
    }
    for (int o = 16; o; o >>= 1){
        s1 += __shfl_xor_sync(0xffffffffu, s1, o);
        s2 += __shfl_xor_sync(0xffffffffu, s2, o);
    }
    if (lane == 0){ g_eW1[w] = s1; g_eW2[w] = s2; }
}

// ---- GEMM: qWq = query_s(3840x1024) @ Wq(1024x1024), stored transposed g_qT[b][d][t] ----
// M-tile of 64 rows == one t (since m = t*64 + b, B=64). grid (N/64, T), 256 thr, 4x4 microtile.
__global__ void k_qwq_gemm(const float* __restrict__ Wq){
    __shared__ float As[16][68];
    __shared__ float Bs[16][64];
    const int tid = threadIdx.x;
    const int t_blk = blockIdx.y;
    const int n0 = blockIdx.x * 64;
    const int m0 = t_blk * 64;
    const int ty = tid / 16, tx = tid % 16;
    const int ar = tid >> 2, ac4 = (tid & 3) << 2;   // A: row ar (0..63), cols ac4..+3
    const int bk = tid >> 4, bn4 = (tid & 15) << 2;  // B: row bk (0..15), cols bn4..+3
    float acc[4][4] = {};
    for (int k0 = 0; k0 < DD; k0 += 16){
        float4 av = *(const float4*)&g_query_s[(size_t)(m0 + ar)*DD + k0 + ac4];
        float4 bv = *(const float4*)&Wq[(size_t)(k0 + bk)*DD + n0 + bn4];
        __syncthreads();
        As[ac4+0][ar] = av.x; As[ac4+1][ar] = av.y;
        As[ac4+2][ar] = av.z; As[ac4+3][ar] = av.w;
        *(float4*)&Bs[bk][bn4] = bv;
        __syncthreads();
        #pragma unroll
        for (int k = 0; k < 16; k++){
            float4 a = *(const float4*)&As[k][ty*4];
            float4 bq = *(const float4*)&Bs[k][tx*4];
            float ai[4] = {a.x, a.y, a.z, a.w};
            float bj[4] = {bq.x, bq.y, bq.z, bq.w};
            #pragma unroll
            for (int i = 0; i < 4; i++)
                #pragma unroll
                for (int j = 0; j < 4; j++)
                    acc[i][j] = fmaf(ai[i], bj[j], acc[i][j]);
        }
    }
    // store transposed: b = ty*4+i, d = n0+tx*4+j, t = t_blk
    #pragma unroll
    for (int i = 0; i < 4; i++)
        #pragma unroll
        for (int j = 0; j < 4; j++)
            g_qT[((size_t)(ty*4 + i)*DD + (n0 + tx*4 + j))*64 + t_blk] = acc[i][j];
}

// ---- Eq[t,b,s] = e[b,s,:] . qWq[t,b,:] : per-b (64s x 64t) tiles, K=D ----
__global__ void k_eq(const float* __restrict__ e){
    __shared__ float Es[16][68];
    __shared__ float Qs[16][64];
    const int tid = threadIdx.x;
    const int b = blockIdx.y;
    const int s0 = blockIdx.x * 64;
    const int ty = tid / 16, tx = tid % 16;
    const int ar = tid >> 2, ac4 = (tid & 3) << 2;
    const int bk = tid >> 4, bt4 = (tid & 15) << 2;
    float acc[4][4] = {};
    for (int k0 = 0; k0 < DD; k0 += 16){
        float4 ev = *(const float4*)&e[(size_t)(b*SS + s0 + ar)*DD + k0 + ac4];
        float4 qv = make_float4(0.f, 0.f, 0.f, 0.f);
        if (bt4 < TT)
            qv = *(const float4*)&g_qT[((size_t)b*DD + k0 + bk)*64 + bt4];
        __syncthreads();
        Es[ac4+0][ar] = ev.x; Es[ac4+1][ar] = ev.y;
        Es[ac4+2][ar] = ev.z; Es[ac4+3][ar] = ev.w;
        *(float4*)&Qs[bk][bt4] = qv;
        __syncthreads();
        #pragma unroll
        for (int k = 0; k < 16; k++){
            float4 a = *(const float4*)&Es[k][ty*4];
            float4 bq = *(const float4*)&Qs[k][tx*4];
            float ai[4] = {a.x, a.y, a.z, a.w};
            float bj[4] = {bq.x, bq.y, bq.z, bq.w};
            #pragma unroll
            for (int i = 0; i < 4; i++)
                #pragma unroll
                for (int j = 0; j < 4; j++)
                    acc[i][j] = fmaf(ai[i], bj[j], acc[i][j]);
        }
    }
    #pragma unroll
    for (int i = 0; i < 4; i++)
        #pragma unroll
        for (int j = 0; j < 4; j++){
            int t = tx*4 + j;
            if (t < TT)
                g_Eq[((size_t)t*BB + b)*SS + (s0 + ty*4 + i)] = acc[i][j];
        }
}

// ---- sequential scalar recurrence: one block per b, thread = s ----
__global__ void k_recur(const float* __restrict__ at, const float* __restrict__ bn){
    const int b = blockIdx.x, s = threadIdx.x;
    const int lane = s & 31, warp = s >> 5;
    float add0 = (s < 50) ? 1.f - (float)(s+1)*0.02f : 0.f;
    float g = add0, a = add0;
    const float ew1 = g_eW1[b*SS + s];
    const float ew2 = g_eW2[b*SS + s];
    const float bnv = bn[0];
    __shared__ float red[8];
    __shared__ float lcs;
    for (int t = 0; t < TT; t++){
        int base = (t*BB + b)*SS + s;
        float aw  = g_attn_w[base];
        float eq  = g_Eq[base];
        float atv = at[(size_t)(b*TT + t)*SS + s];
        g_Wt2[((size_t)b*SS + s)*64 + t] = atv * g;     // sel weight uses pre-update g
        float rp = g_rp[t*BB + b], ap = g_ap[t*BB + b];
        float sim = sigf(g * eq);
        // lcW[b] = sum_s aw*eW2
        float v = aw * ew2;
        for (int o = 16; o; o >>= 1) v += __shfl_xor_sync(0xffffffffu, v, o);
        if (lane == 0) red[warp] = v;
        __syncthreads();
        if (warp == 0){
            float x = (lane < 8) ? red[lane] : 0.f;
            for (int o = 4; o; o >>= 1) x += __shfl_xor_sync(0xffffffffu, x, o);
            if (lane == 0) lcs = x;
        }
        __syncthreads();
        float lc  = lcs;
        float nxt = sigf(ew1 + lc + bnv);
        float c2  = (1.f - a) * ap * nxt;
        g = g * (1.f - rp * aw * sim) + c2;
        a = a + c2;
    }
    // zero t-padding so k_sel needs no inner mask
    for (int t = TT; t < 64; t++)
        g_Wt2[((size_t)b*SS + s)*64 + t] = 0.f;
}

// ---- sel: out[b,t,d] = sum_s Wt2[b,s,t] * e[b,s,d] : per-b (64t x 64d) tiles, K=S ----
__global__ void k_sel(const float* __restrict__ e, float* __restrict__ out){
    __shared__ float Ws[16][64];   // [s_chunk][t]  (no transpose needed)
    __shared__ float Es[16][64];   // [s_chunk][d]
    const int tid = threadIdx.x;
    const int b = blockIdx.y;
    const int d0 = blockIdx.x * 64;
    const int ty = tid / 16, tx = tid % 16;
    const int lk = tid >> 4, lc4 = (tid & 15) << 2;
    float acc[4][4] = {};
    for (int s0 = 0; s0 < SS; s0 += 16){
        float4 wv = *(const float4*)&g_Wt2[((size_t)b*SS + s0 + lk)*64 + lc4];
        float4 ev = *(const float4*)&e[(size_t)(b*SS + s0 + lk)*DD + d0 + lc4];
        __syncthreads();
        *(float4*)&Ws[lk][lc4] = wv;
        *(float4*)&Es[lk][lc4] = ev;
        __syncthreads();
        #pragma unroll
        for (int k = 0; k < 16; k++){
            float4 a = *(const float4*)&Ws[k][ty*4];
            float4 bq = *(const float4*)&Es[k][tx*4];
            float ti[4] = {a.x, a.y, a.z, a.w};
            float dj[4] = {bq.x, bq.y, bq.z, bq.w};
            #pragma unroll
            for (int i = 0; i < 4; i++)
                #pragma unroll
                for (int j = 0; j < 4; j++)
                    acc[i][j] = fmaf(ti[i], dj[j], acc[i][j]);
        }
    }
    #pragma unroll
    for (int i = 0; i < 4; i++){
        int t = ty*4 + i;
        if (t < TT){
            float4 o4 = make_float4(acc[i][0], acc[i][1], acc[i][2], acc[i][3]);
            *(float4*)&out[((size_t)b*TT + t)*DD + d0 + tx*4] = o4;
        }
    }
}

extern "C" void kernel_launch(void* const* d_in, const int* in_sizes, int n_in,
                              void* d_out, int out_size){
    const float* e  = (const float*)d_in[0];
    const float* q  = (const float*)d_in[1];
    const float* at = (const float*)d_in[2];
    const float* Wr = (const float*)d_in[3];
    const float* br = (const float*)d_in[4];
    const float* Wa = (const float*)d_in[5];
    const float* ba = (const float*)d_in[6];
    const float* Wq = (const float*)d_in[7];
    const float* Wn = (const float*)d_in[8];
    const float* bn = (const float*)d_in[9];
    float* out = (float*)d_out;

    k_weights<<<1, 64>>>();
    k_window_attn<<<(TT*BB*SS + 255)/256, 256>>>(at);
    k_window_query<<<(TT*BB*DD + 255)/256, 256>>>(q);
    k_gates<<<(TT*BB*32 + 255)/256, 256>>>(q, Wr, br, Wa, ba);
    k_eW<<<(BB*SS*32 + 255)/256, 256>>>(e, Wn);
    dim3 gg(DD/64, TT);  k_qwq_gemm<<<gg, 256>>>(Wq);
    dim3 ge(SS/64, BB);  k_eq<<<ge, 256>>>(e);
    k_recur<<<BB, SS>>>(at, bn);
    dim3 gs(DD/64, BB);  k_sel<<<gs, 256>>>(e, out);
}

// round 4
// speedup vs baseline: 1.3503x; 1.3503x over previous
#include <cuda_runtime.h>
#include <cuda_bf16.h>
#include <math.h>

#define TT 60
#define BB 64
#define SS 256
#define DD 1024
#define HH 20
#define MTOT (BB*TT)   // 3840 rows of q

// ---- scratch (static device globals) ----
__device__ float g_w[TT][HH];                    // history softmax weights
__device__ float g_attn_w[TT*BB*SS];             // windowed attention [(t*B+b)*S+s]
__device__ __nv_bfloat16 g_Ah[MTOT*DD];          // q split hi   [m=b*T+t][k]
__device__ __nv_bfloat16 g_Al[MTOT*DD];          // q split lo
__device__ __nv_bfloat16 g_BTh[DD*DD];           // Wq^T split hi [n][k]
__device__ __nv_bfloat16 g_BTl[DD*DD];           // Wq^T split lo
__device__ float g_G[MTOT*DD];                   // q @ Wq  [m=b*T+t][d]
__device__ float g_Eq0[TT*BB*SS];                // e . (qWq)      [(t*B+b)*S+s]
__device__ float g_Eq[TT*BB*SS];                 // windowed Eq0
__device__ float g_rp[TT*BB];                    // remove_prob
__device__ float g_ap[TT*BB];                    // add_prob
__device__ float g_lc[TT*BB];                    // sum_s attn_w*eW2
__device__ float g_eW1[BB*SS];                   // e . Wn[:D]
__device__ float g_eW2[BB*SS];                   // e . Wn[D:]
__device__ float g_Wt2[BB*SS*64];                // sel weights attn_i*g_i [b][s][t(pad64)]

__device__ __forceinline__ float sigf(float x){ return 1.0f/(1.0f+expf(-x)); }

#define MMA_BF16(d, a, b0, b1) asm volatile( \
  "mma.sync.aligned.m16n8k16.row.col.f32.bf16.bf16.f32 " \
  "{%0,%1,%2,%3},{%4,%5,%6,%7},{%8,%9},{%0,%1,%2,%3};\n" \
  : "+f"(d[0]), "+f"(d[1]), "+f"(d[2]), "+f"(d[3]) \
  : "r"(a[0]), "r"(a[1]), "r"(a[2]), "r"(a[3]), "r"(b0), "r"(b1))

// ---- step-weight table ----
__global__ void k_weights(){
    int i = threadIdx.x;
    if (i >= TT) return;
    int k = min(i+1, HH);
    float Z = 0.f;
    for (int j = 0; j < k; j++) Z += expf((20.f - (float)j) / 20.f);
    for (int j = 0; j < HH; j++)
        g_w[i][j] = (j < k) ? expf((20.f - (float)j) / 20.f) / Z : 0.f;
}

// ---- split q into bf16 hi/lo ----
__global__ void k_split_q(const float* __restrict__ q){
    int idx = blockIdx.x*blockDim.x + threadIdx.x;
    if (idx >= MTOT*DD) return;
    float x = q[idx];
    __nv_bfloat16 h = __float2bfloat16(x);
    g_Ah[idx] = h;
    g_Al[idx] = __float2bfloat16(x - __bfloat162float(h));
}

// ---- transpose + split Wq: [k][n] -> WqT [n][k] hi/lo ----
__global__ void k_split_Wq(const float* __restrict__ Wq){
    __shared__ float tile[32][33];
    int k0 = blockIdx.y*32, n0 = blockIdx.x*32;
    int tx = threadIdx.x, ty = threadIdx.y;  // (32,8)
    #pragma unroll
    for (int i = 0; i < 32; i += 8)
        tile[ty+i][tx] = Wq[(size_t)(k0+ty+i)*DD + n0+tx];
    __syncthreads();
    #pragma unroll
    for (int i = 0; i < 32; i += 8){
        float x = tile[tx][ty+i];
        __nv_bfloat16 h = __float2bfloat16(x);
        size_t o = (size_t)(n0+ty+i)*DD + k0+tx;
        g_BTh[o] = h;
        g_BTl[o] = __float2bfloat16(x - __bfloat162float(h));
    }
}

// ---- 20-tap window over attns ----
__global__ void k_window_attn(const float* __restrict__ at){
    int idx = blockIdx.x*blockDim.x + threadIdx.x;
    if (idx >= TT*BB*SS) return;
    int s = idx % SS; int b = (idx / SS) % BB; int t = idx / (SS*BB);
    int k = min(t+1, HH);
    float acc = 0.f;
    for (int j = 0; j < k; j++)
        acc = fmaf(g_w[t][j], at[(b*TT + (t-j))*SS + s], acc);
    g_attn_w[idx] = acc;
}

// ---- gates rp/ap[t,b]: one warp per (t,b) ----
__global__ void k_gates(const float* __restrict__ q, const float* __restrict__ Wr,
                        const float* __restrict__ br, const float* __restrict__ Wa,
                        const float* __restrict__ ba){
    int w = (blockIdx.x*blockDim.x + threadIdx.x) >> 5;
    int lane = threadIdx.x & 31;
    if (w >= TT*BB) return;
    int t = w / BB, b = w % BB;
    const float* qr = q + (size_t)(b*TT + t)*DD;
    float s1 = 0.f, s2 = 0.f;
    for (int d = lane*4; d < DD; d += 128){
        float4 qv = *(const float4*)(qr + d);
        float4 r4 = *(const float4*)(Wr + d);
        float4 a4 = *(const float4*)(Wa + d);
        s1 += qv.x*r4.x + qv.y*r4.y + qv.z*r4.z + qv.w*r4.w;
        s2 += qv.x*a4.x + qv.y*a4.y + qv.z*a4.z + qv.w*a4.w;
    }
    for (int o = 16; o; o >>= 1){
        s1 += __shfl_xor_sync(0xffffffffu, s1, o);
        s2 += __shfl_xor_sync(0xffffffffu, s2, o);
    }
    if (lane == 0){
        g_rp[w] = sigf(s1 + br[0]);
        g_ap[w] = sigf(s2 + ba[0]);
    }
}

// ---- eW1/eW2[b,s] ----
__global__ void k_eW(const float* __restrict__ e, const float* __restrict__ Wn){
    int w = (blockIdx.x*blockDim.x + threadIdx.x) >> 5;
    int lane = threadIdx.x & 31;
    if (w >= BB*SS) return;
    const float* er = e + (size_t)w*DD;
    float s1 = 0.f, s2 = 0.f;
    for (int d = lane*4; d < DD; d += 128){
        float4 ev = *(const float4*)(er + d);
        float4 w1 = *(const float4*)(Wn + d);
        float4 w2 = *(const float4*)(Wn + DD + d);
        s1 += ev.x*w1.x + ev.y*w1.y + ev.z*w1.z + ev.w*w1.w;
        s2 += ev.x*w2.x + ev.y*w2.y + ev.z*w2.z + ev.w*w2.w;
    }
    for (int o = 16; o; o >>= 1){
        s1 += __shfl_xor_sync(0xffffffffu, s1, o);
        s2 += __shfl_xor_sync(0xffffffffu, s2, o);
    }
    if (lane == 0){ g_eW1[w] = s1; g_eW2[w] = s2; }
}

// ---- lc[t,b] = sum_s attn_w[t,b,s]*eW2[b,s] : one warp per (t,b) ----
__global__ void k_lc(){
    int w = (blockIdx.x*blockDim.x + threadIdx.x) >> 5;
    int lane = threadIdx.x & 31;
    if (w >= TT*BB) return;
    int b = w % BB;
    const float* aw = g_attn_w + (size_t)w*SS;
    const float* e2 = g_eW2 + b*SS;
    float v = 0.f;
    for (int s = lane*4; s < SS; s += 128){
        float4 a = *(const float4*)&aw[s];
        float4 x = *(const float4*)&e2[s];
        v += a.x*x.x + a.y*x.y + a.z*x.z + a.w*x.w;
    }
    for (int o = 16; o; o >>= 1) v += __shfl_xor_sync(0xffffffffu, v, o);
    if (lane == 0) g_lc[w] = v;
}

// ---- tensor-core GEMM: G[3840,1024] = q @ Wq via bf16-split (3 HMMA products) ----
// block tile 128x128, K-chunk 32, 256 thr = 8 warps (4m x 2n), warp tile 32x64.
__global__ void k_gemm(){
    __shared__ __nv_bfloat16 sAh[128][40], sAl[128][40];
    __shared__ __nv_bfloat16 sBh[128][40], sBl[128][40];
    const int tid = threadIdx.x;
    const int m0 = blockIdx.y * 128;
    const int n0 = blockIdx.x * 128;
    const int wid = tid >> 5, lane = tid & 31;
    const int wm = (wid & 3) * 32;
    const int wn = (wid >> 2) * 64;
    const int lr = tid >> 1;            // gmem load row 0..127
    const int lc0 = (tid & 1) * 16;     // first bf16 col of the two quads {0,16}
    const int lr4 = lane >> 2;          // 0..7
    const int lc2 = (lane & 3) * 2;     // 0,2,4,6

    const size_t aBase = (size_t)(m0 + lr)*DD + lc0;
    const size_t bBase = (size_t)(n0 + lr)*DD + lc0;

    float acc[2][8][4] = {};

    uint4 pAh0 = *(const uint4*)&g_Ah[aBase];
    uint4 pAh1 = *(const uint4*)&g_Ah[aBase + 8];
    uint4 pAl0 = *(const uint4*)&g_Al[aBase];
    uint4 pAl1 = *(const uint4*)&g_Al[aBase + 8];
    uint4 pBh0 = *(const uint4*)&g_BTh[bBase];
    uint4 pBh1 = *(const uint4*)&g_BTh[bBase + 8];
    uint4 pBl0 = *(const uint4*)&g_BTl[bBase];
    uint4 pBl1 = *(const uint4*)&g_BTl[bBase + 8];

    for (int k0 = 0; k0 < DD; k0 += 32){
        *(uint4*)&sAh[lr][lc0]     = pAh0;
        *(uint4*)&sAh[lr][lc0 + 8] = pAh1;
        *(uint4*)&sAl[lr][lc0]     = pAl0;
        *(uint4*)&sAl[lr][lc0 + 8] = pAl1;
        *(uint4*)&sBh[lr][lc0]     = pBh0;
        *(uint4*)&sBh[lr][lc0 + 8] = pBh1;
        *(uint4*)&sBl[lr][lc0]     = pBl0;
        *(uint4*)&sBl[lr][lc0 + 8] = pBl1;
        __syncthreads();
        if (k0 + 32 < DD){
            pAh0 = *(const uint4*)&g_Ah[aBase + k0 + 32];
            pAh1 = *(const uint4*)&g_Ah[aBase + k0 + 40];
            pAl0 = *(const uint4*)&g_Al[aBase + k0 + 32];
            pAl1 = *(const uint4*)&g_Al[aBase + k0 + 40];
            pBh0 = *(const uint4*)&g_BTh[bBase + k0 + 32];
            pBh1 = *(const uint4*)&g_BTh[bBase + k0 + 40];
            pBl0 = *(const uint4*)&g_BTl[bBase + k0 + 32];
            pBl1 = *(const uint4*)&g_BTl[bBase + k0 + 40];
        }
        #pragma unroll
        for (int ks = 0; ks < 32; ks += 16){
            unsigned ah[2][4], al_[2][4];
            #pragma unroll
            for (int mt = 0; mt < 2; mt++){
                int r = wm + mt*16 + lr4;
                ah[mt][0]  = *(const unsigned*)&sAh[r  ][ks + lc2];
                ah[mt][1]  = *(const unsigned*)&sAh[r+8][ks + lc2];
                ah[mt][2]  = *(const unsigned*)&sAh[r  ][ks + lc2 + 8];
                ah[mt][3]  = *(const unsigned*)&sAh[r+8][ks + lc2 + 8];
                al_[mt][0] = *(const unsigned*)&sAl[r  ][ks + lc2];
                al_[mt][1] = *(const unsigned*)&sAl[r+8][ks + lc2];
                al_[mt][2] = *(const unsigned*)&sAl[r  ][ks + lc2 + 8];
                al_[mt][3] = *(const unsigned*)&sAl[r+8][ks + lc2 + 8];
            }
            #pragma unroll
            for (int nt = 0; nt < 8; nt++){
                int c = wn + nt*8 + lr4;
                unsigned bh0 = *(const unsigned*)&sBh[c][ks + lc2];
                unsigned bh1 = *(const unsigned*)&sBh[c][ks + lc2 + 8];
                unsigned bl0 = *(const unsigned*)&sBl[c][ks + lc2];
                unsigned bl1 = *(const unsigned*)&sBl[c][ks + lc2 + 8];
                #pragma unroll
                for (int mt = 0; mt < 2; mt++){
                    MMA_BF16(acc[mt][nt], ah[mt], bh0, bh1);
                    MMA_BF16(acc[mt][nt], ah[mt], bl0, bl1);
                    MMA_BF16(acc[mt][nt], al_[mt], bh0, bh1);
                }
            }
        }
        __syncthreads();
    }
    #pragma unroll
    for (int mt = 0; mt < 2; mt++)
        #pragma unroll
        for (int nt = 0; nt < 8; nt++){
            int row = m0 + wm + mt*16 + lr4;
            int col = n0 + wn + nt*8 + lc2;
            float2 v0 = make_float2(acc[mt][nt][0], acc[mt][nt][1]);
            float2 v1 = make_float2(acc[mt][nt][2], acc[mt][nt][3]);
            *(float2*)&g_G[(size_t)row*DD + col] = v0;
            *(float2*)&g_G[(size_t)(row+8)*DD + col] = v1;
        }
}

// ---- Eq0[t,b,s] = G[b*60+t,:] . e[b,s,:] : per-b (64s x 64t) tiles, K=D ----
__global__ void k_eq0(const float* __restrict__ e){
    __shared__ float Es[16][68];   // [k][s]
    __shared__ float Gs[16][68];   // [k][t]
    const int tid = threadIdx.x;
    const int b = blockIdx.y;
    const int s0 = blockIdx.x * 64;
    const int ty = tid / 16, tx = tid % 16;
    const int ar = tid >> 2, ac4 = (tid & 3) << 2;
    float acc[4][4] = {};
    for (int k0 = 0; k0 < DD; k0 += 16){
        float4 ev = *(const float4*)&e[(size_t)(b*SS + s0 + ar)*DD + k0 + ac4];
        float4 gv = make_float4(0.f,0.f,0.f,0.f);
        if (ar < TT)
            gv = *(const float4*)&g_G[(size_t)(b*TT + ar)*DD + k0 + ac4];
        __syncthreads();
        Es[ac4+0][ar] = ev.x; Es[ac4+1][ar] = ev.y;
        Es[ac4+2][ar] = ev.z; Es[ac4+3][ar] = ev.w;
        Gs[ac4+0][ar] = gv.x; Gs[ac4+1][ar] = gv.y;
        Gs[ac4+2][ar] = gv.z; Gs[ac4+3][ar] = gv.w;
        __syncthreads();
        #pragma unroll
        for (int k = 0; k < 16; k++){
            float4 a = *(const float4*)&Es[k][ty*4];
            float4 g = *(const float4*)&Gs[k][tx*4];
            float ai[4] = {a.x, a.y, a.z, a.w};
            float gj[4] = {g.x, g.y, g.z, g.w};
            #pragma unroll
            for (int i = 0; i < 4; i++)
                #pragma unroll
                for (int j = 0; j < 4; j++)
                    acc[i][j] = fmaf(ai[i], gj[j], acc[i][j]);
        }
    }
    #pragma unroll
    for (int i = 0; i < 4; i++)
        #pragma unroll
        for (int j = 0; j < 4; j++){
            int t = tx*4 + j;
            if (t < TT)
                g_Eq0[((size_t)t*BB + b)*SS + (s0 + ty*4 + i)] = acc[i][j];
        }
}

// ---- 20-tap window over Eq0 -> Eq ----
__global__ void k_window_eq(){
    int idx = blockIdx.x*blockDim.x + threadIdx.x;
    if (idx >= TT*BB*SS) return;
    int s = idx % SS; int b = (idx / SS) % BB; int t = idx / (SS*BB);
    int k = min(t+1, HH);
    float acc = 0.f;
    for (int j = 0; j < k; j++)
        acc = fmaf(g_w[t][j], g_Eq0[((size_t)(t-j)*BB + b)*SS + s], acc);
    g_Eq[idx] = acc;
}

// ---- fully parallel scalar recurrence: one thread per (b,s), no barriers ----
__global__ void k_recur(const float* __restrict__ at, const float* __restrict__ bn){
    int idx = blockIdx.x*blockDim.x + threadIdx.x;
    if (idx >= BB*SS) return;
    const int b = idx / SS, s = idx % SS;
    float add0 = (s < 50) ? 1.f - (float)(s+1)*0.02f : 0.f;
    float g = add0, a = add0;
    const float ew1 = g_eW1[idx];
    const float bnv = bn[0];
    for (int t = 0; t < TT; t++){
        int base = (t*BB + b)*SS + s;
        float aw  = g_attn_w[base];
        float eq  = g_Eq[base];
        float atv = at[(size_t)(b*TT + t)*SS + s];
        g_Wt2[(size_t)idx*64 + t] = atv * g;        // pre-update g
        float rp = g_rp[t*BB + b], ap = g_ap[t*BB + b];
        float lc = g_lc[t*BB + b];
        float sim = sigf(g * eq);
        float nxt = sigf(ew1 + lc + bnv);
        float c2  = (1.f - a) * ap * nxt;
        g = g * (1.f - rp * aw * sim) + c2;
        a = a + c2;
    }
    for (int t = TT; t < 64; t++)
        g_Wt2[(size_t)idx*64 + t] = 0.f;
}

// ---- sel: out[b,t,d] = sum_s Wt2[b,s,t] * e[b,s,d] ----
__global__ void k_sel(const float* __restrict__ e, float* __restrict__ out){
    __shared__ float Ws[16][64];
    __shared__ float Es[16][64];
    const int tid = threadIdx.x;
    const int b = blockIdx.y;
    const int d0 = blockIdx.x * 64;
    const int ty = tid / 16, tx = tid % 16;
    const int lk = tid >> 4, lc4 = (tid & 15) << 2;
    float acc[4][4] = {};
    for (int s0 = 0; s0 < SS; s0 += 16){
        float4 wv = *(const float4*)&g_Wt2[((size_t)b*SS + s0 + lk)*64 + lc4];
        float4 ev = *(const float4*)&e[(size_t)(b*SS + s0 + lk)*DD + d0 + lc4];
        __syncthreads();
        *(float4*)&Ws[lk][lc4] = wv;
        *(float4*)&Es[lk][lc4] = ev;
        __syncthreads();
        #pragma unroll
        for (int k = 0; k < 16; k++){
            float4 a = *(const float4*)&Ws[k][ty*4];
            float4 bq = *(const float4*)&Es[k][tx*4];
            float ti[4] = {a.x, a.y, a.z, a.w};
            float dj[4] = {bq.x, bq.y, bq.z, bq.w};
            #pragma unroll
            for (int i = 0; i < 4; i++)
                #pragma unroll
                for (int j = 0; j < 4; j++)
                    acc[i][j] = fmaf(ti[i], dj[j], acc[i][j]);
        }
    }
    #pragma unroll
    for (int i = 0; i < 4; i++){
        int t = ty*4 + i;
        if (t < TT){
            float4 o4 = make_float4(acc[i][0], acc[i][1], acc[i][2], acc[i][3]);
            *(float4*)&out[((size_t)b*TT + t)*DD + d0 + tx*4] = o4;
        }
    }
}

extern "C" void kernel_launch(void* const* d_in, const int* in_sizes, int n_in,
                              void* d_out, int out_size){
    const float* e  = (const float*)d_in[0];
    const float* q  = (const float*)d_in[1];
    const float* at = (const float*)d_in[2];
    const float* Wr = (const float*)d_in[3];
    const float* br = (const float*)d_in[4];
    const float* Wa = (const float*)d_in[5];
    const float* ba = (const float*)d_in[6];
    const float* Wq = (const float*)d_in[7];
    const float* Wn = (const float*)d_in[8];
    const float* bn = (const float*)d_in[9];
    float* out = (float*)d_out;

    k_weights<<<1, 64>>>();
    k_split_q<<<(MTOT*DD + 255)/256, 256>>>(q);
    { dim3 gw(32, 32); k_split_Wq<<<gw, dim3(32, 8)>>>(Wq); }
    k_window_attn<<<(TT*BB*SS + 255)/256, 256>>>(at);
    k_gates<<<(TT*BB*32 + 255)/256, 256>>>(q, Wr, br, Wa, ba);
    k_eW<<<(BB*SS*32 + 255)/256, 256>>>(e, Wn);
    k_lc<<<(TT*BB*32 + 255)/256, 256>>>();
    { dim3 gg(DD/128, MTOT/128); k_gemm<<<gg, 256>>>(); }
    { dim3 ge(SS/64, BB);        k_eq0<<<ge, 256>>>(e); }
    k_window_eq<<<(TT*BB*SS + 255)/256, 256>>>();
    k_recur<<<(BB*SS + 255)/256, 256>>>(at, bn);
    { dim3 gs(DD/64, BB);        k_sel<<<gs, 256>>>(e, out); }
}

// round 5
// speedup vs baseline: 1.5994x; 1.1844x over previous
#include <cuda_runtime.h>
#include <cuda_bf16.h>
#include <math.h>

#define TT 60
#define BB 64
#define SS 256
#define DD 1024
#define HH 20
#define MTOT (BB*TT)   // 3840 rows of q

// ---- scratch (static device globals) ----
__device__ float g_w[TT][HH];                    // history softmax weights
__device__ float g_attn_w[TT*BB*SS];             // windowed attention [(t*B+b)*S+s]
__device__ __nv_bfloat16 g_Ah[MTOT*DD];          // q split hi   [m=b*T+t][k]
__device__ __nv_bfloat16 g_Al[MTOT*DD];          // q split lo
__device__ __nv_bfloat16 g_BTh[DD*DD];           // Wq^T split hi [n][k]
__device__ __nv_bfloat16 g_BTl[DD*DD];           // Wq^T split lo
__device__ __nv_bfloat16 g_Gh[MTOT*DD];          // (q@Wq) split hi [m][d]
__device__ __nv_bfloat16 g_Gl[MTOT*DD];          // (q@Wq) split lo
__device__ float g_Eq0[TT*BB*SS];                // e . (qWq)  [(t*B+b)*S+s]
__device__ float g_Eq[TT*BB*SS];                 // windowed Eq0
__device__ float g_rp[TT*BB];                    // remove_prob
__device__ float g_ap[TT*BB];                    // add_prob
__device__ float g_lc[TT*BB];                    // sum_s attn_w*eW2
__device__ float g_eW1[BB*SS];                   // e . Wn[:D]
__device__ float g_eW2[BB*SS];                   // e . Wn[D:]
__device__ __nv_bfloat16 g_Wh[BB*64*SS];         // sel weights split hi [b][t(pad64)][s]
__device__ __nv_bfloat16 g_Wl[BB*64*SS];         // sel weights split lo

__device__ __forceinline__ float sigf(float x){ return 1.0f/(1.0f+expf(-x)); }
__device__ __forceinline__ void split1(float x, __nv_bfloat16& h, __nv_bfloat16& l){
    h = __float2bfloat16(x);
    l = __float2bfloat16(x - __bfloat162float(h));
}

#define MMA_BF16(d, a, b0, b1) asm volatile( \
  "mma.sync.aligned.m16n8k16.row.col.f32.bf16.bf16.f32 " \
  "{%0,%1,%2,%3},{%4,%5,%6,%7},{%8,%9},{%0,%1,%2,%3};\n" \
  : "+f"(d[0]), "+f"(d[1]), "+f"(d[2]), "+f"(d[3]) \
  : "r"(a[0]), "r"(a[1]), "r"(a[2]), "r"(a[3]), "r"(b0), "r"(b1))

// ---- step-weight table ----
__global__ void k_weights(){
    int i = threadIdx.x;
    if (i >= TT) return;
    int k = min(i+1, HH);
    float Z = 0.f;
    for (int j = 0; j < k; j++) Z += expf((20.f - (float)j) / 20.f);
    for (int j = 0; j < HH; j++)
        g_w[i][j] = (j < k) ? expf((20.f - (float)j) / 20.f) / Z : 0.f;
}

// ---- transpose + split Wq: [k][n] -> WqT [n][k] hi/lo ----
__global__ void k_split_Wq(const float* __restrict__ Wq){
    __shared__ float tile[32][33];
    int k0 = blockIdx.y*32, n0 = blockIdx.x*32;
    int tx = threadIdx.x, ty = threadIdx.y;  // (32,8)
    #pragma unroll
    for (int i = 0; i < 32; i += 8)
        tile[ty+i][tx] = Wq[(size_t)(k0+ty+i)*DD + n0+tx];
    __syncthreads();
    #pragma unroll
    for (int i = 0; i < 32; i += 8){
        float x = tile[tx][ty+i];
        __nv_bfloat16 h, l; split1(x, h, l);
        size_t o = (size_t)(n0+ty+i)*DD + k0+tx;
        g_BTh[o] = h;
        g_BTl[o] = l;
    }
}

// ---- gates rp/ap[t,b] + q bf16 split: one warp per (t,b) ----
__global__ void k_gates(const float* __restrict__ q, const float* __restrict__ Wr,
                        const float* __restrict__ br, const float* __restrict__ Wa,
                        const float* __restrict__ ba){
    int w = (blockIdx.x*blockDim.x + threadIdx.x) >> 5;
    int lane = threadIdx.x & 31;
    if (w >= TT*BB) return;
    int t = w / BB, b = w % BB;
    const size_t qoff = (size_t)(b*TT + t)*DD;
    const float* qr = q + qoff;
    float s1 = 0.f, s2 = 0.f;
    for (int d = lane*4; d < DD; d += 128){
        float4 qv = *(const float4*)(qr + d);
        float4 r4 = *(const float4*)(Wr + d);
        float4 a4 = *(const float4*)(Wa + d);
        s1 += qv.x*r4.x + qv.y*r4.y + qv.z*r4.z + qv.w*r4.w;
        s2 += qv.x*a4.x + qv.y*a4.y + qv.z*a4.z + qv.w*a4.w;
        __nv_bfloat16 h0,l0,h1,l1,h2,l2,h3,l3;
        split1(qv.x,h0,l0); split1(qv.y,h1,l1); split1(qv.z,h2,l2); split1(qv.w,h3,l3);
        __nv_bfloat162 hh0; hh0.x=h0; hh0.y=h1;
        __nv_bfloat162 hh1; hh1.x=h2; hh1.y=h3;
        __nv_bfloat162 ll0; ll0.x=l0; ll0.y=l1;
        __nv_bfloat162 ll1; ll1.x=l2; ll1.y=l3;
        *(__nv_bfloat162*)&g_Ah[qoff + d]     = hh0;
        *(__nv_bfloat162*)&g_Ah[qoff + d + 2] = hh1;
        *(__nv_bfloat162*)&g_Al[qoff + d]     = ll0;
        *(__nv_bfloat162*)&g_Al[qoff + d + 2] = ll1;
    }
    for (int o = 16; o; o >>= 1){
        s1 += __shfl_xor_sync(0xffffffffu, s1, o);
        s2 += __shfl_xor_sync(0xffffffffu, s2, o);
    }
    if (lane == 0){
        g_rp[w] = sigf(s1 + br[0]);
        g_ap[w] = sigf(s2 + ba[0]);
    }
}

// ---- eW1/eW2[b,s] ----
__global__ void k_eW(const float* __restrict__ e, const float* __restrict__ Wn){
    int w = (blockIdx.x*blockDim.x + threadIdx.x) >> 5;
    int lane = threadIdx.x & 31;
    if (w >= BB*SS) return;
    const float* er = e + (size_t)w*DD;
    float s1 = 0.f, s2 = 0.f;
    for (int d = lane*4; d < DD; d += 128){
        float4 ev = *(const float4*)(er + d);
        float4 w1 = *(const float4*)(Wn + d);
        float4 w2 = *(const float4*)(Wn + DD + d);
        s1 += ev.x*w1.x + ev.y*w1.y + ev.z*w1.z + ev.w*w1.w;
        s2 += ev.x*w2.x + ev.y*w2.y + ev.z*w2.z + ev.w*w2.w;
    }
    for (int o = 16; o; o >>= 1){
        s1 += __shfl_xor_sync(0xffffffffu, s1, o);
        s2 += __shfl_xor_sync(0xffffffffu, s2, o);
    }
    if (lane == 0){ g_eW1[w] = s1; g_eW2[w] = s2; }
}

// ---- windowed attn + fused lc reduce: one block per (t,b), thread = s ----
__global__ void k_window_attn_lc(const float* __restrict__ at){
    const int blk = blockIdx.x;           // = t*BB + b
    const int t = blk / BB, b = blk % BB;
    const int s = threadIdx.x;
    const int lane = s & 31, warp = s >> 5;
    int k = min(t+1, HH);
    float acc = 0.f;
    for (int j = 0; j < k; j++)
        acc = fmaf(g_w[t][j], at[(size_t)(b*TT + (t-j))*SS + s], acc);
    g_attn_w[(size_t)blk*SS + s] = acc;
    float v = acc * g_eW2[b*SS + s];
    __shared__ float red[8];
    for (int o = 16; o; o >>= 1) v += __shfl_xor_sync(0xffffffffu, v, o);
    if (lane == 0) red[warp] = v;
    __syncthreads();
    if (warp == 0){
        float x = (lane < 8) ? red[lane] : 0.f;
        for (int o = 4; o; o >>= 1) x += __shfl_xor_sync(0xffffffffu, x, o);
        if (lane == 0) g_lc[blk] = x;
    }
}

// ---- tensor-core GEMM: G = q @ Wq via bf16-split; epilogue stores split G ----
__global__ __launch_bounds__(256) void k_gemm(){
    __shared__ __nv_bfloat16 sAh[128][40], sAl[128][40];
    __shared__ __nv_bfloat16 sBh[128][40], sBl[128][40];
    const int tid = threadIdx.x;
    const int m0 = blockIdx.y * 128;
    const int n0 = blockIdx.x * 128;
    const int wid = tid >> 5, lane = tid & 31;
    const int wm = (wid & 3) * 32;
    const int wn = (wid >> 2) * 64;
    const int lr = tid >> 1;
    const int lc0 = (tid & 1) * 16;
    const int lr4 = lane >> 2;
    const int lc2 = (lane & 3) * 2;

    const size_t aBase = (size_t)(m0 + lr)*DD + lc0;
    const size_t bBase = (size_t)(n0 + lr)*DD + lc0;

    float acc[2][8][4] = {};

    uint4 pAh0 = *(const uint4*)&g_Ah[aBase];
    uint4 pAh1 = *(const uint4*)&g_Ah[aBase + 8];
    uint4 pAl0 = *(const uint4*)&g_Al[aBase];
    uint4 pAl1 = *(const uint4*)&g_Al[aBase + 8];
    uint4 pBh0 = *(const uint4*)&g_BTh[bBase];
    uint4 pBh1 = *(const uint4*)&g_BTh[bBase + 8];
    uint4 pBl0 = *(const uint4*)&g_BTl[bBase];
    uint4 pBl1 = *(const uint4*)&g_BTl[bBase + 8];

    for (int k0 = 0; k0 < DD; k0 += 32){
        *(uint4*)&sAh[lr][lc0]     = pAh0;
        *(uint4*)&sAh[lr][lc0 + 8] = pAh1;
        *(uint4*)&sAl[lr][lc0]     = pAl0;
        *(uint4*)&sAl[lr][lc0 + 8] = pAl1;
        *(uint4*)&sBh[lr][lc0]     = pBh0;
        *(uint4*)&sBh[lr][lc0 + 8] = pBh1;
        *(uint4*)&sBl[lr][lc0]     = pBl0;
        *(uint4*)&sBl[lr][lc0 + 8] = pBl1;
        __syncthreads();
        if (k0 + 32 < DD){
            pAh0 = *(const uint4*)&g_Ah[aBase + k0 + 32];
            pAh1 = *(const uint4*)&g_Ah[aBase + k0 + 40];
            pAl0 = *(const uint4*)&g_Al[aBase + k0 + 32];
            pAl1 = *(const uint4*)&g_Al[aBase + k0 + 40];
            pBh0 = *(const uint4*)&g_BTh[bBase + k0 + 32];
            pBh1 = *(const uint4*)&g_BTh[bBase + k0 + 40];
            pBl0 = *(const uint4*)&g_BTl[bBase + k0 + 32];
            pBl1 = *(const uint4*)&g_BTl[bBase + k0 + 40];
        }
        #pragma unroll
        for (int ks = 0; ks < 32; ks += 16){
            unsigned ah[2][4], al_[2][4];
            #pragma unroll
            for (int mt = 0; mt < 2; mt++){
                int r = wm + mt*16 + lr4;
                ah[mt][0]  = *(const unsigned*)&sAh[r  ][ks + lc2];
                ah[mt][1]  = *(const unsigned*)&sAh[r+8][ks + lc2];
                ah[mt][2]  = *(const unsigned*)&sAh[r  ][ks + lc2 + 8];
                ah[mt][3]  = *(const unsigned*)&sAh[r+8][ks + lc2 + 8];
                al_[mt][0] = *(const unsigned*)&sAl[r  ][ks + lc2];
                al_[mt][1] = *(const unsigned*)&sAl[r+8][ks + lc2];
                al_[mt][2] = *(const unsigned*)&sAl[r  ][ks + lc2 + 8];
                al_[mt][3] = *(const unsigned*)&sAl[r+8][ks + lc2 + 8];
            }
            #pragma unroll
            for (int nt = 0; nt < 8; nt++){
                int c = wn + nt*8 + lr4;
                unsigned bh0 = *(const unsigned*)&sBh[c][ks + lc2];
                unsigned bh1 = *(const unsigned*)&sBh[c][ks + lc2 + 8];
                unsigned bl0 = *(const unsigned*)&sBl[c][ks + lc2];
                unsigned bl1 = *(const unsigned*)&sBl[c][ks + lc2 + 8];
                #pragma unroll
                for (int mt = 0; mt < 2; mt++){
                    MMA_BF16(acc[mt][nt], ah[mt], bh0, bh1);
                    MMA_BF16(acc[mt][nt], ah[mt], bl0, bl1);
                    MMA_BF16(acc[mt][nt], al_[mt], bh0, bh1);
                }
            }
        }
        __syncthreads();
    }
    #pragma unroll
    for (int mt = 0; mt < 2; mt++)
        #pragma unroll
        for (int nt = 0; nt < 8; nt++){
            int row = m0 + wm + mt*16 + lr4;
            int col = n0 + wn + nt*8 + lc2;
            #pragma unroll
            for (int rr = 0; rr < 2; rr++){
                float x = acc[mt][nt][rr*2], y = acc[mt][nt][rr*2+1];
                __nv_bfloat16 hx,lx,hy,ly;
                split1(x,hx,lx); split1(y,hy,ly);
                __nv_bfloat162 hh; hh.x=hx; hh.y=hy;
                __nv_bfloat162 ll; ll.x=lx; ll.y=ly;
                size_t o = (size_t)(row + rr*8)*DD + col;
                *(__nv_bfloat162*)&g_Gh[o] = hh;
                *(__nv_bfloat162*)&g_Gl[o] = ll;
            }
        }
}

// ---- tensor-core Eq0: per-b C[s,t] = e[b,s,:].G[b,t,:], M=64 s, N=64 t, K=1024 ----
__global__ __launch_bounds__(256) void k_eq0(const float* __restrict__ e){
    __shared__ __nv_bfloat16 sAh[64][72], sAl[64][72];
    __shared__ __nv_bfloat16 sBh[64][72], sBl[64][72];
    const int tid = threadIdx.x;
    const int b = blockIdx.y;
    const int s0 = blockIdx.x * 64;
    const int wid = tid >> 5, lane = tid & 31;
    const int wm = (wid & 1) * 32;
    const int wn = (wid >> 1) * 16;
    const int lr4 = lane >> 2, lc2 = (lane & 3) * 2;
    const int lr = tid >> 2;            // staging row 0..63
    const int kq = (tid & 3) * 16;      // k offset (floats / bf16)

    const size_t aRow = (size_t)(b*SS + s0 + lr)*DD;
    const bool bv = lr < TT;
    const size_t bRow = (size_t)(b*TT + (bv ? lr : 0))*DD;

    float acc[2][2][4] = {};

    for (int k0 = 0; k0 < DD; k0 += 64){
        // load A (e fp32, 16 consecutive floats per thread) + B (G split, uint4s)
        float4 av[4];
        #pragma unroll
        for (int q4 = 0; q4 < 4; q4++)
            av[q4] = *(const float4*)&e[aRow + k0 + kq + q4*4];
        uint4 z = make_uint4(0,0,0,0);
        uint4 bh0 = bv ? *(const uint4*)&g_Gh[bRow + k0 + kq]     : z;
        uint4 bh1 = bv ? *(const uint4*)&g_Gh[bRow + k0 + kq + 8] : z;
        uint4 bl0 = bv ? *(const uint4*)&g_Gl[bRow + k0 + kq]     : z;
        uint4 bl1 = bv ? *(const uint4*)&g_Gl[bRow + k0 + kq + 8] : z;
        __syncthreads();
        #pragma unroll
        for (int q4 = 0; q4 < 4; q4++){
            float vv[4] = {av[q4].x, av[q4].y, av[q4].z, av[q4].w};
            #pragma unroll
            for (int u = 0; u < 4; u += 2){
                __nv_bfloat16 h0,l0,h1,l1;
                split1(vv[u],h0,l0); split1(vv[u+1],h1,l1);
                __nv_bfloat162 hh; hh.x=h0; hh.y=h1;
                __nv_bfloat162 ll; ll.x=l0; ll.y=l1;
                *(__nv_bfloat162*)&sAh[lr][kq + q4*4 + u] = hh;
                *(__nv_bfloat162*)&sAl[lr][kq + q4*4 + u] = ll;
            }
        }
        *(uint4*)&sBh[lr][kq]     = bh0;
        *(uint4*)&sBh[lr][kq + 8] = bh1;
        *(uint4*)&sBl[lr][kq]     = bl0;
        *(uint4*)&sBl[lr][kq + 8] = bl1;
        __syncthreads();
        #pragma unroll
        for (int ks = 0; ks < 64; ks += 16){
            unsigned ah[2][4], al_[2][4];
            #pragma unroll
            for (int mf = 0; mf < 2; mf++){
                int r = wm + mf*16 + lr4;
                ah[mf][0]  = *(const unsigned*)&sAh[r  ][ks + lc2];
                ah[mf][1]  = *(const unsigned*)&sAh[r+8][ks + lc2];
                ah[mf][2]  = *(const unsigned*)&sAh[r  ][ks + lc2 + 8];
                ah[mf][3]  = *(const unsigned*)&sAh[r+8][ks + lc2 + 8];
                al_[mf][0] = *(const unsigned*)&sAl[r  ][ks + lc2];
                al_[mf][1] = *(const unsigned*)&sAl[r+8][ks + lc2];
                al_[mf][2] = *(const unsigned*)&sAl[r  ][ks + lc2 + 8];
                al_[mf][3] = *(const unsigned*)&sAl[r+8][ks + lc2 + 8];
            }
            #pragma unroll
            for (int nf = 0; nf < 2; nf++){
                int c = wn + nf*8 + lr4;
                unsigned bh0r = *(const unsigned*)&sBh[c][ks + lc2];
                unsigned bh1r = *(const unsigned*)&sBh[c][ks + lc2 + 8];
                unsigned bl0r = *(const unsigned*)&sBl[c][ks + lc2];
                unsigned bl1r = *(const unsigned*)&sBl[c][ks + lc2 + 8];
                #pragma unroll
                for (int mf = 0; mf < 2; mf++){
                    MMA_BF16(acc[mf][nf], ah[mf], bh0r, bh1r);
                    MMA_BF16(acc[mf][nf], ah[mf], bl0r, bl1r);
                    MMA_BF16(acc[mf][nf], al_[mf], bh0r, bh1r);
                }
            }
        }
        __syncthreads();
    }
    #pragma unroll
    for (int mf = 0; mf < 2; mf++)
        #pragma unroll
        for (int nf = 0; nf < 2; nf++){
            int s = s0 + wm + mf*16 + lr4;
            int t0 = wn + nf*8 + lc2;
            if (t0 < TT){
                g_Eq0[((size_t)t0*BB + b)*SS + s]       = acc[mf][nf][0];
                g_Eq0[((size_t)t0*BB + b)*SS + s + 8]   = acc[mf][nf][2];
            }
            if (t0 + 1 < TT){
                g_Eq0[((size_t)(t0+1)*BB + b)*SS + s]     = acc[mf][nf][1];
                g_Eq0[((size_t)(t0+1)*BB + b)*SS + s + 8] = acc[mf][nf][3];
            }
        }
}

// ---- 20-tap window over Eq0 -> Eq ----
__global__ void k_window_eq(){
    int idx = blockIdx.x*blockDim.x + threadIdx.x;
    if (idx >= TT*BB*SS) return;
    int s = idx % SS; int b = (idx / SS) % BB; int t = idx / (SS*BB);
    int k = min(t+1, HH);
    float acc = 0.f;
    for (int j = 0; j < k; j++)
        acc = fmaf(g_w[t][j], g_Eq0[((size_t)(t-j)*BB + b)*SS + s], acc);
    g_Eq[idx] = acc;
}

// ---- scalar recurrence; emits split+transposed sel weights [b][t][s] ----
__global__ void k_recur(const float* __restrict__ at, const float* __restrict__ bn){
    int idx = blockIdx.x*blockDim.x + threadIdx.x;
    if (idx >= BB*SS) return;
    const int b = idx / SS, s = idx % SS;
    float add0 = (s < 50) ? 1.f - (float)(s+1)*0.02f : 0.f;
    float g = add0, a = add0;
    const float ew1 = g_eW1[idx];
    const float bnv = bn[0];
    for (int t = 0; t < TT; t++){
        int base = (t*BB + b)*SS + s;
        float aw  = g_attn_w[base];
        float eq  = g_Eq[base];
        float atv = at[(size_t)(b*TT + t)*SS + s];
        float w = atv * g;                          // pre-update g
        __nv_bfloat16 h, l; split1(w, h, l);
        size_t wo = ((size_t)(b*64 + t))*SS + s;
        g_Wh[wo] = h; g_Wl[wo] = l;
        float rp = g_rp[t*BB + b], ap = g_ap[t*BB + b];
        float lc = g_lc[t*BB + b];
        float sim = sigf(g * eq);
        float nxt = sigf(ew1 + lc + bnv);
        float c2  = (1.f - a) * ap * nxt;
        g = g * (1.f - rp * aw * sim) + c2;
        a = a + c2;
    }
    __nv_bfloat16 zz = __float2bfloat16(0.f);
    for (int t = TT; t < 64; t++){
        size_t wo = ((size_t)(b*64 + t))*SS + s;
        g_Wh[wo] = zz; g_Wl[wo] = zz;
    }
}

// ---- tensor-core sel: per-b out[t,d] = sum_s W[t,s]*e[s,d], M=64 t, N=128 d, K=256 s ----
__global__ __launch_bounds__(256) void k_sel(const float* __restrict__ e, float* __restrict__ out){
    __shared__ __nv_bfloat16 sWh[64][40], sWl[64][40];
    __shared__ __nv_bfloat16 sEh[128][40], sEl[128][40];
    const int tid = threadIdx.x;
    const int b = blockIdx.y;
    const int d0 = blockIdx.x * 128;
    const int wid = tid >> 5, lane = tid & 31;
    const int wm = (wid & 1) * 32;
    const int wn = (wid >> 1) * 32;
    const int lr4 = lane >> 2, lc2 = (lane & 3) * 2;
    // W staging (threads < 128): row wr, k group
    const int wr = tid >> 1, wkg = (tid & 1) * 16;
    // E staging (all 256): row er (s_local), col group cg
    const int er = tid & 31, cg = tid >> 5;

    float acc[2][4][4] = {};

    for (int s0 = 0; s0 < SS; s0 += 32){
        uint4 wv0, wv1, wl0, wl1;
        if (tid < 128){
            size_t o = ((size_t)(b*64 + wr))*SS + s0 + wkg;
            wv0 = *(const uint4*)&g_Wh[o];
            wv1 = *(const uint4*)&g_Wh[o + 8];
            wl0 = *(const uint4*)&g_Wl[o];
            wl1 = *(const uint4*)&g_Wl[o + 8];
        }
        float4 ev[4];
        #pragma unroll
        for (int q4 = 0; q4 < 4; q4++)
            ev[q4] = *(const float4*)&e[(size_t)(b*SS + s0 + er)*DD + d0 + cg*16 + q4*4];
        __syncthreads();
        if (tid < 128){
            *(uint4*)&sWh[wr][wkg]     = wv0;
            *(uint4*)&sWh[wr][wkg + 8] = wv1;
            *(uint4*)&sWl[wr][wkg]     = wl0;
            *(uint4*)&sWl[wr][wkg + 8] = wl1;
        }
        #pragma unroll
        for (int q4 = 0; q4 < 4; q4++){
            float vv[4] = {ev[q4].x, ev[q4].y, ev[q4].z, ev[q4].w};
            #pragma unroll
            for (int u = 0; u < 4; u++){
                __nv_bfloat16 h, l; split1(vv[u], h, l);
                int d_local = cg*16 + q4*4 + u;
                sEh[d_local][er] = h;
                sEl[d_local][er] = l;
            }
        }
        __syncthreads();
        #pragma unroll
        for (int ks = 0; ks < 32; ks += 16){
            unsigned ah[2][4], al_[2][4];
            #pragma unroll
            for (int mf = 0; mf < 2; mf++){
                int r = wm + mf*16 + lr4;
                ah[mf][0]  = *(const unsigned*)&sWh[r  ][ks + lc2];
                ah[mf][1]  = *(const unsigned*)&sWh[r+8][ks + lc2];
                ah[mf][2]  = *(const unsigned*)&sWh[r  ][ks + lc2 + 8];
                ah[mf][3]  = *(const unsigned*)&sWh[r+8][ks + lc2 + 8];
                al_[mf][0] = *(const unsigned*)&sWl[r  ][ks + lc2];
                al_[mf][1] = *(const unsigned*)&sWl[r+8][ks + lc2];
                al_[mf][2] = *(const unsigned*)&sWl[r  ][ks + lc2 + 8];
                al_[mf][3] = *(const unsigned*)&sWl[r+8][ks + lc2 + 8];
            }
            #pragma unroll
            for (int nf = 0; nf < 4; nf++){
                int c = wn + nf*8 + lr4;
                unsigned bh0 = *(const unsigned*)&sEh[c][ks + lc2];
                unsigned bh1 = *(const unsigned*)&sEh[c][ks + lc2 + 8];
                unsigned bl0 = *(const unsigned*)&sEl[c][ks + lc2];
                unsigned bl1 = *(const unsigned*)&sEl[c][ks + lc2 + 8];
                #pragma unroll
                for (int mf = 0; mf < 2; mf++){
                    MMA_BF16(acc[mf][nf], ah[mf], bh0, bh1);
                    MMA_BF16(acc[mf][nf], ah[mf], bl0, bl1);
                    MMA_BF16(acc[mf][nf], al_[mf], bh0, bh1);
                }
            }
        }
        __syncthreads();
    }
    #pragma unroll
    for (int mf = 0; mf < 2; mf++)
        #pragma unroll
        for (int nf = 0; nf < 4; nf++){
            int d = d0 + wn + nf*8 + lc2;
            #pragma unroll
            for (int rr = 0; rr < 2; rr++){
                int t = wm + mf*16 + lr4 + rr*8;
                if (t < TT){
                    float2 v = make_float2(acc[mf][nf][rr*2], acc[mf][nf][rr*2+1]);
                    *(float2*)&out[((size_t)b*TT + t)*DD + d] = v;
                }
            }
        }
}

extern "C" void kernel_launch(void* const* d_in, const int* in_sizes, int n_in,
                              void* d_out, int out_size){
    const float* e  = (const float*)d_in[0];
    const float* q  = (const float*)d_in[1];
    const float* at = (const float*)d_in[2];
    const float* Wr = (const float*)d_in[3];
    const float* br = (const float*)d_in[4];
    const float* Wa = (const float*)d_in[5];
    const float* ba = (const float*)d_in[6];
    const float* Wq = (const float*)d_in[7];
    const float* Wn = (const float*)d_in[8];
    const float* bn = (const float*)d_in[9];
    float* out = (float*)d_out;

    k_weights<<<1, 64>>>();
    { dim3 gw(32, 32); k_split_Wq<<<gw, dim3(32, 8)>>>(Wq); }
    k_gates<<<(TT*BB*32 + 255)/256, 256>>>(q, Wr, br, Wa, ba);
    k_eW<<<(BB*SS*32 + 255)/256, 256>>>(e, Wn);
    k_window_attn_lc<<<TT*BB, SS>>>(at);
    { dim3 gg(DD/128, MTOT/128); k_gemm<<<gg, 256>>>(); }
    { dim3 ge(SS/64, BB);        k_eq0<<<ge, 256>>>(e); }
    k_window_eq<<<(TT*BB*SS + 255)/256, 256>>>();
    k_recur<<<(BB*SS + 255)/256, 256>>>(at, bn);
    { dim3 gs(DD/128, BB);       k_sel<<<gs, 256>>>(e, out); }
}

// round 7
// speedup vs baseline: 1.8949x; 1.1847x over previous
#include <cuda_runtime.h>
#include <cuda_bf16.h>
#include <cstdint>
#include <math.h>

#define TT 60
#define BB 64
#define SS 256
#define DD 1024
#define HH 20
#define MTOT (BB*TT)   // 3840 rows of q

// ---- scratch (static device globals) ----
__device__ float g_w[TT][HH];                    // history softmax weights
__device__ float g_attn_w[TT*BB*SS];             // windowed attention [(t*B+b)*S+s]
__device__ __nv_bfloat16 g_Ah[MTOT*DD];          // q split hi   [m=b*T+t][k]
__device__ __nv_bfloat16 g_Al[MTOT*DD];          // q split lo
__device__ __nv_bfloat16 g_BTh[DD*DD];           // Wq^T split hi [n][k]
__device__ __nv_bfloat16 g_BTl[DD*DD];           // Wq^T split lo
__device__ __nv_bfloat16 g_Gh[MTOT*DD];          // (q@Wq) split hi [m][d]
__device__ __nv_bfloat16 g_Gl[MTOT*DD];          // (q@Wq) split lo
__device__ float g_Eq0[TT*BB*SS];                // e . (qWq)  [(t*B+b)*S+s]
__device__ float g_Eq[TT*BB*SS];                 // windowed Eq0
__device__ float g_rp[TT*BB];                    // remove_prob
__device__ float g_ap[TT*BB];                    // add_prob
__device__ float g_lc[TT*BB];                    // sum_s attn_w*eW2
__device__ float g_eW1[BB*SS];                   // e . Wn[:D]
__device__ float g_eW2[BB*SS];                   // e . Wn[D:]
__device__ __nv_bfloat16 g_Wh[BB*64*SS];         // sel weights split hi [b][t(pad64)][s]
__device__ __nv_bfloat16 g_Wl[BB*64*SS];         // sel weights split lo

__device__ __forceinline__ float sigf(float x){ return 1.0f/(1.0f+expf(-x)); }
__device__ __forceinline__ void split1(float x, __nv_bfloat16& h, __nv_bfloat16& l){
    h = __float2bfloat16(x);
    l = __float2bfloat16(x - __bfloat162float(h));
}
__device__ __forceinline__ uint32_t s2u(const void* p){
    return (uint32_t)__cvta_generic_to_shared(p);
}

#define MMA_BF16(d, a, b0, b1) asm volatile( \
  "mma.sync.aligned.m16n8k16.row.col.f32.bf16.bf16.f32 " \
  "{%0,%1,%2,%3},{%4,%5,%6,%7},{%8,%9},{%0,%1,%2,%3};\n" \
  : "+f"(d[0]), "+f"(d[1]), "+f"(d[2]), "+f"(d[3]) \
  : "r"(a[0]), "r"(a[1]), "r"(a[2]), "r"(a[3]), "r"(b0), "r"(b1))

#define LDSM_X4(r, addr) asm volatile( \
  "ldmatrix.sync.aligned.m8n8.x4.shared.b16 {%0,%1,%2,%3},[%4];\n" \
  : "=r"((r)[0]), "=r"((r)[1]), "=r"((r)[2]), "=r"((r)[3]) : "r"(addr))

// ---- step-weight table ----
__global__ void k_weights(){
    int i = threadIdx.x;
    if (i >= TT) return;
    int k = min(i+1, HH);
    float Z = 0.f;
    for (int j = 0; j < k; j++) Z += expf((20.f - (float)j) / 20.f);
    for (int j = 0; j < HH; j++)
        g_w[i][j] = (j < k) ? expf((20.f - (float)j) / 20.f) / Z : 0.f;
}

// ---- transpose + split Wq: [k][n] -> WqT [n][k] hi/lo ----
__global__ void k_split_Wq(const float* __restrict__ Wq){
    __shared__ float tile[32][33];
    int k0 = blockIdx.y*32, n0 = blockIdx.x*32;
    int tx = threadIdx.x, ty = threadIdx.y;  // (32,8)
    #pragma unroll
    for (int i = 0; i < 32; i += 8)
        tile[ty+i][tx] = Wq[(size_t)(k0+ty+i)*DD + n0+tx];
    __syncthreads();
    #pragma unroll
    for (int i = 0; i < 32; i += 8){
        float x = tile[tx][ty+i];
        __nv_bfloat16 h, l; split1(x, h, l);
        size_t o = (size_t)(n0+ty+i)*DD + k0+tx;
        g_BTh[o] = h;
        g_BTl[o] = l;
    }
}

// ---- gates rp/ap[t,b] + q bf16 split: one warp per (t,b) ----
__global__ void k_gates(const float* __restrict__ q, const float* __restrict__ Wr,
                        const float* __restrict__ br, const float* __restrict__ Wa,
                        const float* __restrict__ ba){
    int w = (blockIdx.x*blockDim.x + threadIdx.x) >> 5;
    int lane = threadIdx.x & 31;
    if (w >= TT*BB) return;
    int t = w / BB, b = w % BB;
    const size_t qoff = (size_t)(b*TT + t)*DD;
    const float* qr = q + qoff;
    float s1 = 0.f, s2 = 0.f;
    for (int d = lane*4; d < DD; d += 128){
        float4 qv = *(const float4*)(qr + d);
        float4 r4 = *(const float4*)(Wr + d);
        float4 a4 = *(const float4*)(Wa + d);
        s1 += qv.x*r4.x + qv.y*r4.y + qv.z*r4.z + qv.w*r4.w;
        s2 += qv.x*a4.x + qv.y*a4.y + qv.z*a4.z + qv.w*a4.w;
        __nv_bfloat16 h0,l0,h1,l1,h2,l2,h3,l3;
        split1(qv.x,h0,l0); split1(qv.y,h1,l1); split1(qv.z,h2,l2); split1(qv.w,h3,l3);
        __nv_bfloat162 hh0; hh0.x=h0; hh0.y=h1;
        __nv_bfloat162 hh1; hh1.x=h2; hh1.y=h3;
        __nv_bfloat162 ll0; ll0.x=l0; ll0.y=l1;
        __nv_bfloat162 ll1; ll1.x=l2; ll1.y=l3;
        *(__nv_bfloat162*)&g_Ah[qoff + d]     = hh0;
        *(__nv_bfloat162*)&g_Ah[qoff + d + 2] = hh1;
        *(__nv_bfloat162*)&g_Al[qoff + d]     = ll0;
        *(__nv_bfloat162*)&g_Al[qoff + d + 2] = ll1;
    }
    for (int o = 16; o; o >>= 1){
        s1 += __shfl_xor_sync(0xffffffffu, s1, o);
        s2 += __shfl_xor_sync(0xffffffffu, s2, o);
    }
    if (lane == 0){
        g_rp[w] = sigf(s1 + br[0]);
        g_ap[w] = sigf(s2 + ba[0]);
    }
}

// ---- windowed attn + fused lc reduce: one block per (t,b), thread = s ----
__global__ void k_window_attn_lc(const float* __restrict__ at){
    const int blk = blockIdx.x;           // = t*BB + b
    const int t = blk / BB, b = blk % BB;
    const int s = threadIdx.x;
    const int lane = s & 31, warp = s >> 5;
    int k = min(t+1, HH);
    float acc = 0.f;
    for (int j = 0; j < k; j++)
        acc = fmaf(g_w[t][j], at[(size_t)(b*TT + (t-j))*SS + s], acc);
    g_attn_w[(size_t)blk*SS + s] = acc;
    float v = acc * g_eW2[b*SS + s];
    __shared__ float red[8];
    for (int o = 16; o; o >>= 1) v += __shfl_xor_sync(0xffffffffu, v, o);
    if (lane == 0) red[warp] = v;
    __syncthreads();
    if (warp == 0){
        float x = (lane < 8) ? red[lane] : 0.f;
        for (int o = 4; o; o >>= 1) x += __shfl_xor_sync(0xffffffffu, x, o);
        if (lane == 0) g_lc[blk] = x;
    }
}

// ---- tensor-core GEMM: G = q @ Wq via bf16-split, LDSM fragments ----
__global__ __launch_bounds__(256) void k_gemm(){
    __shared__ __align__(16) __nv_bfloat16 sAh[128][40], sAl[128][40];
    __shared__ __align__(16) __nv_bfloat16 sBh[128][40], sBl[128][40];
    const int tid = threadIdx.x;
    const int m0 = blockIdx.y * 128;
    const int n0 = blockIdx.x * 128;
    const int wid = tid >> 5, lane = tid & 31;
    const int wm = (wid & 3) * 32;
    const int wn = (wid >> 2) * 64;
    const int lr = tid >> 1;
    const int lc0 = (tid & 1) * 16;

    // ldmatrix lane->address selectors (A-order and B-order differ)
    const int rsA = (lane & 7) + ((lane >> 3) & 1) * 8;
    const int kbA = ((lane >> 4) & 1) * 16;          // byte offset
    const int rsB = (lane & 7) + ((lane >> 4) & 1) * 8;
    const int kbB = ((lane >> 3) & 1) * 16;
    const uint32_t aH = s2u(&sAh[wm + rsA][0]) + kbA;
    const uint32_t aL = s2u(&sAl[wm + rsA][0]) + kbA;
    const uint32_t bH = s2u(&sBh[wn + rsB][0]) + kbB;
    const uint32_t bL = s2u(&sBl[wn + rsB][0]) + kbB;

    const size_t aBase = (size_t)(m0 + lr)*DD + lc0;
    const size_t bBase = (size_t)(n0 + lr)*DD + lc0;

    float acc[2][8][4] = {};

    uint4 pAh0 = *(const uint4*)&g_Ah[aBase];
    uint4 pAh1 = *(const uint4*)&g_Ah[aBase + 8];
    uint4 pAl0 = *(const uint4*)&g_Al[aBase];
    uint4 pAl1 = *(const uint4*)&g_Al[aBase + 8];
    uint4 pBh0 = *(const uint4*)&g_BTh[bBase];
    uint4 pBh1 = *(const uint4*)&g_BTh[bBase + 8];
    uint4 pBl0 = *(const uint4*)&g_BTl[bBase];
    uint4 pBl1 = *(const uint4*)&g_BTl[bBase + 8];

    for (int k0 = 0; k0 < DD; k0 += 32){
        *(uint4*)&sAh[lr][lc0]     = pAh0;
        *(uint4*)&sAh[lr][lc0 + 8] = pAh1;
        *(uint4*)&sAl[lr][lc0]     = pAl0;
        *(uint4*)&sAl[lr][lc0 + 8] = pAl1;
        *(uint4*)&sBh[lr][lc0]     = pBh0;
        *(uint4*)&sBh[lr][lc0 + 8] = pBh1;
        *(uint4*)&sBl[lr][lc0]     = pBl0;
        *(uint4*)&sBl[lr][lc0 + 8] = pBl1;
        __syncthreads();
        if (k0 + 32 < DD){
            pAh0 = *(const uint4*)&g_Ah[aBase + k0 + 32];
            pAh1 = *(const uint4*)&g_Ah[aBase + k0 + 40];
            pAl0 = *(const uint4*)&g_Al[aBase + k0 + 32];
            pAl1 = *(const uint4*)&g_Al[aBase + k0 + 40];
            pBh0 = *(const uint4*)&g_BTh[bBase + k0 + 32];
            pBh1 = *(const uint4*)&g_BTh[bBase + k0 + 40];
            pBl0 = *(const uint4*)&g_BTl[bBase + k0 + 32];
            pBl1 = *(const uint4*)&g_BTl[bBase + k0 + 40];
        }
        #pragma unroll
        for (int ks = 0; ks < 32; ks += 16){
            const int ksb = ks * 2;
            unsigned ah[2][4], al_[2][4];
            LDSM_X4(ah[0],  aH + ksb);
            LDSM_X4(ah[1],  aH + 16*80 + ksb);
            LDSM_X4(al_[0], aL + ksb);
            LDSM_X4(al_[1], aL + 16*80 + ksb);
            #pragma unroll
            for (int p = 0; p < 4; p++){
                unsigned bh[4], bl[4];
                LDSM_X4(bh, bH + p*16*80 + ksb);
                LDSM_X4(bl, bL + p*16*80 + ksb);
                #pragma unroll
                for (int mt = 0; mt < 2; mt++){
                    MMA_BF16(acc[mt][2*p],   ah[mt],  bh[0], bh[1]);
                    MMA_BF16(acc[mt][2*p],   ah[mt],  bl[0], bl[1]);
                    MMA_BF16(acc[mt][2*p],   al_[mt], bh[0], bh[1]);
                    MMA_BF16(acc[mt][2*p+1], ah[mt],  bh[2], bh[3]);
                    MMA_BF16(acc[mt][2*p+1], ah[mt],  bl[2], bl[3]);
                    MMA_BF16(acc[mt][2*p+1], al_[mt], bh[2], bh[3]);
                }
            }
        }
        __syncthreads();
    }
    const int lr4 = lane >> 2;
    const int lc2 = (lane & 3) * 2;
    #pragma unroll
    for (int mt = 0; mt < 2; mt++)
        #pragma unroll
        for (int nt = 0; nt < 8; nt++){
            int row = m0 + wm + mt*16 + lr4;
            int col = n0 + wn + nt*8 + lc2;
            #pragma unroll
            for (int rr = 0; rr < 2; rr++){
                float x = acc[mt][nt][rr*2], y = acc[mt][nt][rr*2+1];
                __nv_bfloat16 hx,lx,hy,ly;
                split1(x,hx,lx); split1(y,hy,ly);
                __nv_bfloat162 hh; hh.x=hx; hh.y=hy;
                __nv_bfloat162 ll; ll.x=lx; ll.y=ly;
                size_t o = (size_t)(row + rr*8)*DD + col;
                *(__nv_bfloat162*)&g_Gh[o] = hh;
                *(__nv_bfloat162*)&g_Gl[o] = ll;
            }
        }
}

// ---- tensor-core Eq0 + fused eW: per-b C[s,t] = e[b,s,:].G[b,t,:] ----
__global__ __launch_bounds__(256) void k_eq0(const float* __restrict__ e,
                                             const float* __restrict__ Wn){
    __shared__ __align__(16) __nv_bfloat16 sAh[64][72], sAl[64][72];
    __shared__ __align__(16) __nv_bfloat16 sBh[64][72], sBl[64][72];
    const int tid = threadIdx.x;
    const int b = blockIdx.y;
    const int s0 = blockIdx.x * 64;
    const int wid = tid >> 5, lane = tid & 31;
    const int wm = (wid & 1) * 32;
    const int wn = (wid >> 1) * 16;
    const int lr = tid >> 2;            // staging row 0..63
    const int kq = (tid & 3) * 16;      // k offset

    const int rsA = (lane & 7) + ((lane >> 3) & 1) * 8;
    const int kbA = ((lane >> 4) & 1) * 16;
    const int rsB = (lane & 7) + ((lane >> 4) & 1) * 8;
    const int kbB = ((lane >> 3) & 1) * 16;
    const uint32_t aH = s2u(&sAh[wm + rsA][0]) + kbA;
    const uint32_t aL = s2u(&sAl[wm + rsA][0]) + kbA;
    const uint32_t bH = s2u(&sBh[wn + rsB][0]) + kbB;
    const uint32_t bL = s2u(&sBl[wn + rsB][0]) + kbB;

    const size_t aRow = (size_t)(b*SS + s0 + lr)*DD;
    const bool bv = lr < TT;
    const size_t bRow = (size_t)(b*TT + (bv ? lr : 0))*DD;

    float acc[2][2][4] = {};
    float s1 = 0.f, s2 = 0.f;   // fused eW dots for row lr (partial over kq)

    for (int k0 = 0; k0 < DD; k0 += 64){
        float4 av[4];
        #pragma unroll
        for (int q4 = 0; q4 < 4; q4++){
            av[q4] = *(const float4*)&e[aRow + k0 + kq + q4*4];
            float4 w1 = *(const float4*)&Wn[k0 + kq + q4*4];
            float4 w2 = *(const float4*)&Wn[DD + k0 + kq + q4*4];
            s1 += av[q4].x*w1.x + av[q4].y*w1.y + av[q4].z*w1.z + av[q4].w*w1.w;
            s2 += av[q4].x*w2.x + av[q4].y*w2.y + av[q4].z*w2.z + av[q4].w*w2.w;
        }
        uint4 z = make_uint4(0,0,0,0);
        uint4 gh0 = bv ? *(const uint4*)&g_Gh[bRow + k0 + kq]     : z;
        uint4 gh1 = bv ? *(const uint4*)&g_Gh[bRow + k0 + kq + 8] : z;
        uint4 gl0 = bv ? *(const uint4*)&g_Gl[bRow + k0 + kq]     : z;
        uint4 gl1 = bv ? *(const uint4*)&g_Gl[bRow + k0 + kq + 8] : z;
        __syncthreads();
        #pragma unroll
        for (int q4 = 0; q4 < 4; q4++){
            float vv[4] = {av[q4].x, av[q4].y, av[q4].z, av[q4].w};
            #pragma unroll
            for (int u = 0; u < 4; u += 2){
                __nv_bfloat16 h0,l0,h1,l1;
                split1(vv[u],h0,l0); split1(vv[u+1],h1,l1);
                __nv_bfloat162 hh; hh.x=h0; hh.y=h1;
                __nv_bfloat162 ll; ll.x=l0; ll.y=l1;
                *(__nv_bfloat162*)&sAh[lr][kq + q4*4 + u] = hh;
                *(__nv_bfloat162*)&sAl[lr][kq + q4*4 + u] = ll;
            }
        }
        *(uint4*)&sBh[lr][kq]     = gh0;
        *(uint4*)&sBh[lr][kq + 8] = gh1;
        *(uint4*)&sBl[lr][kq]     = gl0;
        *(uint4*)&sBl[lr][kq + 8] = gl1;
        __syncthreads();
        #pragma unroll
        for (int ks = 0; ks < 64; ks += 16){
            const int ksb = ks * 2;
            unsigned ah[2][4], al_[2][4], bh[4], bl[4];
            LDSM_X4(ah[0],  aH + ksb);
            LDSM_X4(ah[1],  aH + 16*144 + ksb);
            LDSM_X4(al_[0], aL + ksb);
            LDSM_X4(al_[1], aL + 16*144 + ksb);
            LDSM_X4(bh, bH + ksb);
            LDSM_X4(bl, bL + ksb);
            #pragma unroll
            for (int mf = 0; mf < 2; mf++){
                MMA_BF16(acc[mf][0], ah[mf],  bh[0], bh[1]);
                MMA_BF16(acc[mf][0], ah[mf],  bl[0], bl[1]);
                MMA_BF16(acc[mf][0], al_[mf], bh[0], bh[1]);
                MMA_BF16(acc[mf][1], ah[mf],  bh[2], bh[3]);
                MMA_BF16(acc[mf][1], ah[mf],  bl[2], bl[3]);
                MMA_BF16(acc[mf][1], al_[mf], bh[2], bh[3]);
            }
        }
        __syncthreads();
    }
    // fused eW reduction: 4 threads share row lr (consecutive lanes)
    s1 += __shfl_xor_sync(0xffffffffu, s1, 1);
    s1 += __shfl_xor_sync(0xffffffffu, s1, 2);
    s2 += __shfl_xor_sync(0xffffffffu, s2, 1);
    s2 += __shfl_xor_sync(0xffffffffu, s2, 2);
    if ((tid & 3) == 0){
        g_eW1[b*SS + s0 + lr] = s1;
        g_eW2[b*SS + s0 + lr] = s2;
    }
    const int lr4 = lane >> 2;
    const int lc2 = (lane & 3) * 2;
    #pragma unroll
    for (int mf = 0; mf < 2; mf++)
        #pragma unroll
        for (int nf = 0; nf < 2; nf++){
            int s = s0 + wm + mf*16 + lr4;
            int t0 = wn + nf*8 + lc2;
            if (t0 < TT){
                g_Eq0[((size_t)t0*BB + b)*SS + s]       = acc[mf][nf][0];
                g_Eq0[((size_t)t0*BB + b)*SS + s + 8]   = acc[mf][nf][2];
            }
            if (t0 + 1 < TT){
                g_Eq0[((size_t)(t0+1)*BB + b)*SS + s]     = acc[mf][nf][1];
                g_Eq0[((size_t)(t0+1)*BB + b)*SS + s + 8] = acc[mf][nf][3];
            }
        }
}

// ---- 20-tap window over Eq0 -> Eq ----
__global__ void k_window_eq(){
    int idx = blockIdx.x*blockDim.x + threadIdx.x;
    if (idx >= TT*BB*SS) return;
    int s = idx % SS; int b = (idx / SS) % BB; int t = idx / (SS*BB);
    int k = min(t+1, HH);
    float acc = 0.f;
    for (int j = 0; j < k; j++)
        acc = fmaf(g_w[t][j], g_Eq0[((size_t)(t-j)*BB + b)*SS + s], acc);
    g_Eq[idx] = acc;
}

// ---- scalar recurrence; emits split+transposed sel weights [b][t][s] ----
__global__ void k_recur(const float* __restrict__ at, const float* __restrict__ bn){
    int idx = blockIdx.x*blockDim.x + threadIdx.x;
    if (idx >= BB*SS) return;
    const int b = idx / SS, s = idx % SS;
    float add0 = (s < 50) ? 1.f - (float)(s+1)*0.02f : 0.f;
    float g = add0, a = add0;
    const float ew1 = g_eW1[idx];
    const float bnv = bn[0];
    for (int t = 0; t < TT; t++){
        int base = (t*BB + b)*SS + s;
        float aw  = g_attn_w[base];
        float eq  = g_Eq[base];
        float atv = at[(size_t)(b*TT + t)*SS + s];
        float w = atv * g;                          // pre-update g
        __nv_bfloat16 h, l; split1(w, h, l);
        size_t wo = ((size_t)(b*64 + t))*SS + s;
        g_Wh[wo] = h; g_Wl[wo] = l;
        float rp = g_rp[t*BB + b], ap = g_ap[t*BB + b];
        float lc = g_lc[t*BB + b];
        float sim = sigf(g * eq);
        float nxt = sigf(ew1 + lc + bnv);
        float c2  = (1.f - a) * ap * nxt;
        g = g * (1.f - rp * aw * sim) + c2;
        a = a + c2;
    }
    __nv_bfloat16 zz = __float2bfloat16(0.f);
    for (int t = TT; t < 64; t++){
        size_t wo = ((size_t)(b*64 + t))*SS + s;
        g_Wh[wo] = zz; g_Wl[wo] = zz;
    }
}

// ---- tensor-core sel: per-b out[t,d] = sum_s W[t,s]*e[s,d] ----
__global__ __launch_bounds__(256) void k_sel(const float* __restrict__ e, float* __restrict__ out){
    __shared__ __align__(16) __nv_bfloat16 sWh[64][40], sWl[64][40];
    __shared__ __align__(16) __nv_bfloat16 sEh[128][40], sEl[128][40];
    const int tid = threadIdx.x;
    const int b = blockIdx.y;
    const int d0 = blockIdx.x * 128;
    const int wid = tid >> 5, lane = tid & 31;
    const int wm = (wid & 1) * 32;
    const int wn = (wid >> 1) * 32;
    // W staging (threads < 128): row wr, k group
    const int wr = tid >> 1, wkg = (tid & 1) * 16;
    // E staging (all 256): row er (s_local), col group cg
    const int er = tid & 31, cg = tid >> 5;

    const int rsA = (lane & 7) + ((lane >> 3) & 1) * 8;
    const int kbA = ((lane >> 4) & 1) * 16;
    const int rsB = (lane & 7) + ((lane >> 4) & 1) * 8;
    const int kbB = ((lane >> 3) & 1) * 16;
    const uint32_t aH = s2u(&sWh[wm + rsA][0]) + kbA;
    const uint32_t aL = s2u(&sWl[wm + rsA][0]) + kbA;
    const uint32_t bH = s2u(&sEh[wn + rsB][0]) + kbB;
    const uint32_t bL = s2u(&sEl[wn + rsB][0]) + kbB;

    float acc[2][4][4] = {};

    for (int s0 = 0; s0 < SS; s0 += 32){
        uint4 wv0, wv1, wl0, wl1;
        if (tid < 128){
            size_t o = ((size_t)(b*64 + wr))*SS + s0 + wkg;
            wv0 = *(const uint4*)&g_Wh[o];
            wv1 = *(const uint4*)&g_Wh[o + 8];
            wl0 = *(const uint4*)&g_Wl[o];
            wl1 = *(const uint4*)&g_Wl[o + 8];
        }
        float4 ev[4];
        #pragma unroll
        for (int q4 = 0; q4 < 4; q4++)
            ev[q4] = *(const float4*)&e[(size_t)(b*SS + s0 + er)*DD + d0 + cg*16 + q4*4];
        __syncthreads();
        if (tid < 128){
            *(uint4*)&sWh[wr][wkg]     = wv0;
            *(uint4*)&sWh[wr][wkg + 8] = wv1;
            *(uint4*)&sWl[wr][wkg]     = wl0;
            *(uint4*)&sWl[wr][wkg + 8] = wl1;
        }
        #pragma unroll
        for (int q4 = 0; q4 < 4; q4++){
            float vv[4] = {ev[q4].x, ev[q4].y, ev[q4].z, ev[q4].w};
            #pragma unroll
            for (int u = 0; u < 4; u++){
                __nv_bfloat16 h, l; split1(vv[u], h, l);
                int d_local = cg*16 + q4*4 + u;
                sEh[d_local][er] = h;
                sEl[d_local][er] = l;
            }
        }
        __syncthreads();
        #pragma unroll
        for (int ks = 0; ks < 32; ks += 16){
            const int ksb = ks * 2;
            unsigned ah[2][4], al_[2][4];
            LDSM_X4(ah[0],  aH + ksb);
            LDSM_X4(ah[1],  aH + 16*80 + ksb);
            LDSM_X4(al_[0], aL + ksb);
            LDSM_X4(al_[1], aL + 16*80 + ksb);
            #pragma unroll
            for (int p = 0; p < 2; p++){
                unsigned bh[4], bl[4];
                LDSM_X4(bh, bH + p*16*80 + ksb);
                LDSM_X4(bl, bL + p*16*80 + ksb);
                #pragma unroll
                for (int mf = 0; mf < 2; mf++){
                    MMA_BF16(acc[mf][2*p],   ah[mf],  bh[0], bh[1]);
                    MMA_BF16(acc[mf][2*p],   ah[mf],  bl[0], bl[1]);
                    MMA_BF16(acc[mf][2*p],   al_[mf], bh[0], bh[1]);
                    MMA_BF16(acc[mf][2*p+1], ah[mf],  bh[2], bh[3]);
                    MMA_BF16(acc[mf][2*p+1], ah[mf],  bl[2], bl[3]);
                    MMA_BF16(acc[mf][2*p+1], al_[mf], bh[2], bh[3]);
                }
            }
        }
        __syncthreads();
    }
    const int lr4 = lane >> 2;
    const int lc2 = (lane & 3) * 2;
    #pragma unroll
    for (int mf = 0; mf < 2; mf++)
        #pragma unroll
        for (int nf = 0; nf < 4; nf++){
            int d = d0 + wn + nf*8 + lc2;
            #pragma unroll
            for (int rr = 0; rr < 2; rr++){
                int t = wm + mf*16 + lr4 + rr*8;
                if (t < TT){
                    float2 v = make_float2(acc[mf][nf][rr*2], acc[mf][nf][rr*2+1]);
                    *(float2*)&out[((size_t)b*TT + t)*DD + d] = v;
                }
            }
        }
}

extern "C" void kernel_launch(void* const* d_in, const int* in_sizes, int n_in,
                              void* d_out, int out_size){
    const float* e  = (const float*)d_in[0];
    const float* q  = (const float*)d_in[1];
    const float* at = (const float*)d_in[2];
    const float* Wr = (const float*)d_in[3];
    const float* br = (const float*)d_in[4];
    const float* Wa = (const float*)d_in[5];
    const float* ba = (const float*)d_in[6];
    const float* Wq = (const float*)d_in[7];
    const float* Wn = (const float*)d_in[8];
    const float* bn = (const float*)d_in[9];
    float* out = (float*)d_out;

    k_weights<<<1, 64>>>();
    { dim3 gw(32, 32); k_split_Wq<<<gw, dim3(32, 8)>>>(Wq); }
    k_gates<<<(TT*BB*32 + 255)/256, 256>>>(q, Wr, br, Wa, ba);
    { dim3 gg(DD/128, MTOT/128); k_gemm<<<gg, 256>>>(); }
    { dim3 ge(SS/64, BB);        k_eq0<<<ge, 256>>>(e, Wn); }
    k_window_attn_lc<<<TT*BB, SS>>>(at);
    k_window_eq<<<(TT*BB*SS + 255)/256, 256>>>();
    k_recur<<<(BB*SS + 255)/256, 256>>>(at, bn);
    { dim3 gs(DD/128, BB);       k_sel<<<gs, 256>>>(e, out); }
}